// round 15
// baseline (speedup 1.0000x reference)
#include <cuda_runtime.h>
#include <cstdint>
#include <cstddef>

#define N_TFH 1000
#define N_TG  20000
#define N_E   4000000
#define NV    (N_E / 4)            // 1,000,000 groups of 4 edges
#define GRID    148
#define THREADS 512
#define NTILES  ((NV + THREADS - 1) / THREADS)   // 1954
#define STAGES  3
#define ARRS    9
#define ARR_STRIDE  (THREADS * 16)               // 8192 B per array per stage
#define STAGE_BYTES (ARRS * ARR_STRIDE)          // 73,728 B
#define SMEM_TOTAL  (STAGES * STAGE_BYTES)       // 221,184 B

// Precomputed gather tables (device scratch, rebuilt by prep each call).
__device__ float2 g_tf_tab[N_TG + N_TFH];  // (mu, 1/sigma^2)
__device__ float2 g_tg_tab[N_TG];          // (mu, sigma^2)
// Cross-kernel accumulator; zero at every entry (last block restores it).
__device__ float    g_sum;
__device__ unsigned g_ticket;

__device__ __forceinline__ float warp_reduce(float v) {
    #pragma unroll
    for (int o = 16; o > 0; o >>= 1)
        v += __shfl_xor_sync(0xFFFFFFFFu, v, o);
    return v;
}

// FFMA-pipe reciprocal (2 Newton) and log (~1e-7 rel). No MUFU.
__device__ __forceinline__ float fast_rcp(float x) {
    float r = __int_as_float(0x7EF311C3 - __float_as_int(x));
    r = r * fmaf(-x, r, 2.0f);
    r = r * fmaf(-x, r, 2.0f);
    return r;
}
__device__ __forceinline__ float fast_logf(float a) {
    int e = (__float_as_int(a) - 0x3f2aaaab) & 0xff800000;
    float m = __int_as_float(__float_as_int(a) - e);
    float i = (float)e * 1.19209290e-7f;
    float f = m - 1.0f;
    float s = f * f;
    float r = fmaf(0.230836749f, f, -0.279208571f);
    float t = fmaf(0.331826031f, f, -0.498910338f);
    r = fmaf(r, s, t);
    r = fmaf(r, s, f);
    r = fmaf(i, 0.693147182f, r);
    return r;
}

__device__ __forceinline__ uint32_t smem_u32(const void* p) {
    uint32_t a;
    asm("{ .reg .u64 t; cvta.to.shared.u64 t, %1; cvt.u32.u64 %0, t; }"
        : "=r"(a) : "l"(p));
    return a;
}
__device__ __forceinline__ void cp16(uint32_t dst, const void* src, int pred) {
    asm volatile(
        "{ .reg .pred p; setp.ne.u32 p, %2, 0;\n\t"
        "@p cp.async.cg.shared.global [%0], [%1], 16; }"
        :: "r"(dst), "l"(src), "r"(pred) : "memory");
}
__device__ __forceinline__ void cp_commit() {
    asm volatile("cp.async.commit_group;" ::: "memory");
}
template <int N>
__device__ __forceinline__ void cp_wait() {
    asm volatile("cp.async.wait_group %0;" :: "n"(N) : "memory");
}

// Prep: build gather tables + accumulate p/q terms into g_sum.
__global__ void prep_kernel(const float* __restrict__ TF_high_mu,
                            const float* __restrict__ TF_high_sigma,
                            const float* __restrict__ TG_mu,
                            const float* __restrict__ TG_sigma,
                            const float* __restrict__ TF_high_exp,
                            const float* __restrict__ TG_exp,
                            const int*   __restrict__ father_num) {
    const float HALF_LOG2PI = 0.918938533204672742f;
    int i = blockIdx.x * blockDim.x + threadIdx.x;
    float acc = 0.0f;
    if (i < N_TG) {
        float mu = TG_mu[i], sg = TG_sigma[i];
        float s2 = sg * sg;
        g_tf_tab[i] = make_float2(mu, 1.0f / s2);
        g_tg_tab[i] = make_float2(mu, s2);
        // q term
        float x = TG_exp[i];
        float fn = (float)father_num[i];
        float z = (x - mu) / sg;
        float lp = -0.5f * z * z - fast_logf(sg) - HALF_LOG2PI;
        acc += (fn - 1.0f) * lp;
    }
    if (i < N_TFH) {
        float mu = TF_high_mu[i], sg = TF_high_sigma[i];
        g_tf_tab[N_TG + i] = make_float2(mu, 1.0f / (sg * sg));
        // p term
        float x = TF_high_exp[i];
        float z = (x - mu) / sg;
        acc += 0.5f * z * z + fast_logf(sg) + HALF_LOG2PI;
    }
    acc = warp_reduce(acc);
    __shared__ float ws[8];
    int lane = threadIdx.x & 31, wid = threadIdx.x >> 5;
    if (lane == 0) ws[wid] = acc;
    __syncthreads();
    if (wid == 0) {
        float v = (lane < (int)(blockDim.x >> 5)) ? ws[lane] : 0.0f;
        v = warp_reduce(v);
        if (lane == 0) atomicAdd(&g_sum, v);
    }
}

__global__ __launch_bounds__(THREADS, 1)
void fused_loss_kernel(
    const char* __restrict__ k_edge,
    const char* __restrict__ alpha,
    const char* __restrict__ cov,
    const char* __restrict__ edge_y,
    const char* __restrict__ edge_x,
    const char* __restrict__ idx_tf_tg,
    const char* __restrict__ idx_tf_high,
    const char* __restrict__ edge_tg_idx,
    const char* __restrict__ is_high,
    float* __restrict__ out)
{
    extern __shared__ char smem[];
    const float HALF_LOG2PI = 0.918938533204672742f;
    const int tid = threadIdx.x;
    const uint32_t my_base = smem_u32(smem) + tid * 16;

    const char* srcs[ARRS] = { k_edge, alpha, cov, edge_y, edge_x,
                               idx_tf_tg, idx_tf_high, edge_tg_idx, is_high };

    // ---- issue one tile's 9 x 16B into stage s (per-thread, predicated) ----
    auto issue = [&](int t, int s) {
        int v = t * THREADS + tid;
        int pred = (v < NV);
        size_t off = (size_t)v * 16;
        uint32_t dst = my_base + s * STAGE_BYTES;
        #pragma unroll
        for (int a = 0; a < ARRS; a++)
            cp16(dst + a * ARR_STRIDE, srcs[a] + off, pred);
        cp_commit();
    };

    // ---- prologue: fill all 3 stages ----
    #pragma unroll
    for (int s = 0; s < STAGES; s++)
        issue(blockIdx.x + s * GRID, s);

    float acc = 0.0f;
    int k = 0;
    for (int t = blockIdx.x; t < NTILES; t += GRID, k++) {
        const int stage = k % STAGES;
        cp_wait<STAGES - 1>();           // oldest group (this stage) complete

        const int v = t * THREADS + tid;
        if (v < NV) {
            const char* st = smem + stage * STAGE_BYTES + tid * 16;
            float4 ke = *(const float4*)(st + 0 * ARR_STRIDE);
            float4 al = *(const float4*)(st + 1 * ARR_STRIDE);
            float4 cv = *(const float4*)(st + 2 * ARR_STRIDE);
            float4 ey = *(const float4*)(st + 3 * ARR_STRIDE);
            float4 ex = *(const float4*)(st + 4 * ARR_STRIDE);
            int4  itg = *(const int4*)(st + 5 * ARR_STRIDE);
            int4  ith = *(const int4*)(st + 6 * ARR_STRIDE);
            int4  ieg = *(const int4*)(st + 7 * ARR_STRIDE);
            int4  ih  = *(const int4*)(st + 8 * ARR_STRIDE);

            const float* kef = &ke.x; const float* alf = &al.x;
            const float* cvf = &cv.x; const float* eyf = &ey.x;
            const float* exf = &ex.x;
            const int* itgf = &itg.x; const int* ithf = &ith.x;
            const int* iegf = &ieg.x; const int* ihf  = &ih.x;

            #pragma unroll
            for (int l = 0; l < 4; l++) {
                int tfi = ihf[l] ? (N_TG + ithf[l]) : itgf[l];
                float2 tf = __ldg(&g_tf_tab[tfi]);   // (mu, 1/sig^2)
                float2 tg = __ldg(&g_tg_tab[iegf[l]]); // (mu, sig^2)

                float iv  = tf.y;
                float loc = fmaf(kef[l] * cvf[l], (eyf[l] - tf.x) * iv, tg.x);
                loc = fmaxf(loc, 0.0f) + 0.01f;
                float var = fmaf(-alf[l] * alf[l], iv, tg.y);
                var = fmaxf(var, 0.0f) + 0.01f;

                float dx = exf[l] - loc;
                acc += fmaf(0.5f, fmaf(dx * dx, fast_rcp(var), fast_logf(var)),
                            HALF_LOG2PI);
            }
        }
        // refill this stage with the tile 3 ahead (empty commit keeps count).
        issue(t + STAGES * GRID, stage);
    }
    cp_wait<0>();   // drain

    // ---- block reduction -> cross-block self-resetting accumulate ----
    acc = warp_reduce(acc);
    __shared__ float warp_sums[THREADS / 32];
    int lane = tid & 31, wid = tid >> 5;
    if (lane == 0) warp_sums[wid] = acc;
    __syncthreads();
    if (wid == 0) {
        float v = (lane < THREADS / 32) ? warp_sums[lane] : 0.0f;
        v = warp_reduce(v);
        if (lane == 0) {
            atomicAdd(&g_sum, v);
            __threadfence();
            unsigned t = atomicInc(&g_ticket, GRID - 1);   // wraps to 0
            if (t == GRID - 1)
                out[0] = atomicExch(&g_sum, 0.0f);         // publish + reset
        }
    }
}

extern "C" void kernel_launch(void* const* d_in, const int* in_sizes, int n_in,
                              void* d_out, int out_size) {
    cudaFuncSetAttribute(fused_loss_kernel,
                         cudaFuncAttributeMaxDynamicSharedMemorySize, SMEM_TOTAL);

    prep_kernel<<<(N_TG + 255) / 256, 256>>>(
        (const float*)d_in[0], (const float*)d_in[1],
        (const float*)d_in[2], (const float*)d_in[3],
        (const float*)d_in[4], (const float*)d_in[5],
        (const int*)d_in[11]);

    fused_loss_kernel<<<GRID, THREADS, SMEM_TOTAL>>>(
        (const char*)d_in[6],  (const char*)d_in[7],
        (const char*)d_in[8],  (const char*)d_in[9],
        (const char*)d_in[10],
        (const char*)d_in[12], (const char*)d_in[13],
        (const char*)d_in[14], (const char*)d_in[15],
        (float*)d_out);
}

// round 17
// speedup vs baseline: 1.9796x; 1.9796x over previous
#include <cuda_runtime.h>
#include <cuda_fp16.h>
#include <cstdint>
#include <cstddef>

#define N_TFH 1000
#define N_TG  20000
#define N_E   4000000
#define NV    (N_E / 4)              // 1,000,000 groups of 4 edges
#define N_TAB (N_TG + N_TFH)         // 21,000
#define GRID    148
#define THREADS 384
#define TILE_V  THREADS              // 384 groups per tile
#define STAGES  2
#define NTILES  ((NV + TILE_V - 1) / TILE_V)   // 2605
#define ARRS    9
#define ARR_BYTES   (TILE_V * 16)              // 6,144 per array per stage
#define STAGE_BYTES (ARRS * ARR_BYTES)         // 55,296
#define TAB_BYTES   (N_TAB * 4)                // 84,000 (half2 table)
#define SMEM_TOTAL  (STAGES * STAGE_BYTES + TAB_BYTES)   // 194,592

// Cross-block accumulator; zero at every entry (last block restores it).
__device__ float    g_sum;
__device__ unsigned g_ticket;

__device__ __forceinline__ float warp_reduce(float v) {
    #pragma unroll
    for (int o = 16; o > 0; o >>= 1)
        v += __shfl_xor_sync(0xFFFFFFFFu, v, o);
    return v;
}
// FFMA-pipe reciprocal (2 Newton) and log (~1e-7 rel). No MUFU.
__device__ __forceinline__ float fast_rcp(float x) {
    float r = __int_as_float(0x7EF311C3 - __float_as_int(x));
    r = r * fmaf(-x, r, 2.0f);
    r = r * fmaf(-x, r, 2.0f);
    return r;
}
__device__ __forceinline__ float fast_logf(float a) {
    int e = (__float_as_int(a) - 0x3f2aaaab) & 0xff800000;
    float m = __int_as_float(__float_as_int(a) - e);
    float i = (float)e * 1.19209290e-7f;
    float f = m - 1.0f;
    float s = f * f;
    float r = fmaf(0.230836749f, f, -0.279208571f);
    float t = fmaf(0.331826031f, f, -0.498910338f);
    r = fmaf(r, s, t);
    r = fmaf(r, s, f);
    r = fmaf(i, 0.693147182f, r);
    return r;
}

__device__ __forceinline__ uint32_t smem_u32(const void* p) {
    uint32_t a;
    asm("{ .reg .u64 t; cvta.to.shared.u64 t, %1; cvt.u32.u64 %0, t; }"
        : "=r"(a) : "l"(p));
    return a;
}
__device__ __forceinline__ void mbar_init(uint32_t mbar, uint32_t cnt) {
    asm volatile("mbarrier.init.shared.b64 [%0], %1;" :: "r"(mbar), "r"(cnt) : "memory");
}
__device__ __forceinline__ void mbar_expect_tx(uint32_t mbar, uint32_t bytes) {
    asm volatile("mbarrier.arrive.expect_tx.shared.b64 _, [%0], %1;"
                 :: "r"(mbar), "r"(bytes) : "memory");
}
__device__ __forceinline__ void mbar_wait(uint32_t mbar, uint32_t parity) {
    asm volatile(
        "{\n\t.reg .pred P;\n\t"
        "WL%=:\n\t"
        "mbarrier.try_wait.parity.acquire.cta.shared::cta.b64 P, [%0], %1, 0x989680;\n\t"
        "@P bra WD%=;\n\t"
        "bra WL%=;\n\t"
        "WD%=:\n\t}"
        :: "r"(mbar), "r"(parity) : "memory");
}
__device__ __forceinline__ void fence_async_shared() {
    asm volatile("fence.proxy.async.shared::cta;" ::: "memory");
}
__device__ __forceinline__ void tma_1d(uint32_t dst, const void* src,
                                       uint32_t bytes, uint32_t mbar) {
    asm volatile(
        "cp.async.bulk.shared::cta.global.mbarrier::complete_tx::bytes [%0], [%1], %2, [%3];"
        :: "r"(dst), "l"(src), "r"(bytes), "r"(mbar) : "memory");
}

__global__ __launch_bounds__(THREADS, 1)
void fused_loss_kernel(
    const float* __restrict__ TF_high_mu,
    const float* __restrict__ TF_high_sigma,
    const float* __restrict__ TG_mu,
    const float* __restrict__ TG_sigma,
    const float* __restrict__ TF_high_exp,
    const float* __restrict__ TG_exp,
    const char* __restrict__ k_edge,
    const char* __restrict__ alpha,
    const char* __restrict__ cov,
    const char* __restrict__ edge_y,
    const char* __restrict__ edge_x,
    const int*  __restrict__ father_num,
    const char* __restrict__ idx_tf_tg,
    const char* __restrict__ idx_tf_high,
    const char* __restrict__ edge_tg_idx,
    const char* __restrict__ is_high,
    float* __restrict__ out)
{
    extern __shared__ char smem[];
    __shared__ uint64_t s_mbar[STAGES];
    __shared__ float warp_sums[THREADS / 32];

    __half2* s_tab = (__half2*)(smem + STAGES * STAGE_BYTES);
    const uint32_t smem_base = smem_u32(smem);
    const uint32_t mbar0 = smem_u32(&s_mbar[0]);
    const int tid = threadIdx.x;
    const float HALF_LOG2PI = 0.918938533204672742f;

    const char* srcs[ARRS] = { k_edge, alpha, cov, edge_y, edge_x,
                               idx_tf_tg, idx_tf_high, edge_tg_idx, is_high };

    // ---- build fp16 (mu, sigma^2) table; init mbarriers ----
    for (int i = tid; i < N_TG; i += THREADS) {
        float sg = TG_sigma[i];
        s_tab[i] = __floats2half2_rn(TG_mu[i], sg * sg);
    }
    for (int i = tid; i < N_TFH; i += THREADS) {
        float sg = TF_high_sigma[i];
        s_tab[N_TG + i] = __floats2half2_rn(TF_high_mu[i], sg * sg);
    }
    if (tid == 0) {
        mbar_init(mbar0 + 0, 1);
        mbar_init(mbar0 + 8, 1);
        fence_async_shared();
    }
    __syncthreads();

    // ---- prologue: fill both stages (tiles bid, bid+GRID — always full) ----
    if (tid == 0) {
        #pragma unroll
        for (int s = 0; s < STAGES; s++) {
            int t = blockIdx.x + s * GRID;
            size_t off = (size_t)t * ARR_BYTES;
            uint32_t dst = smem_base + s * STAGE_BYTES;
            mbar_expect_tx(mbar0 + s * 8, ARRS * ARR_BYTES);
            #pragma unroll
            for (int a = 0; a < ARRS; a++)
                tma_1d(dst + a * ARR_BYTES, srcs[a] + off, ARR_BYTES, mbar0 + s * 8);
        }
    }

    float acc = 0.0f;

    // ---- p/q terms (GRID*THREADS = 56,832 covers N_TG) ----
    const int gtid = blockIdx.x * THREADS + tid;
    if (gtid < N_TG) {
        float mu = TG_mu[gtid], sg = TG_sigma[gtid], x = TG_exp[gtid];
        float fn = (float)father_num[gtid];
        float z = (x - mu) / sg;
        float lp = -0.5f * z * z - fast_logf(sg) - HALF_LOG2PI;
        acc += (fn - 1.0f) * lp;                            // -q
    }
    if (gtid < N_TFH) {
        float mu = TF_high_mu[gtid], sg = TF_high_sigma[gtid], x = TF_high_exp[gtid];
        float z = (x - mu) / sg;
        acc += 0.5f * z * z + fast_logf(sg) + HALF_LOG2PI;  // -p
    }

    // ---- main loop: double-buffered TMA tiles ----
    int ph0 = 0, ph1 = 0;
    int k = 0;
    for (int t = blockIdx.x; t < NTILES; t += GRID, k++) {
        const int s = k & 1;
        if (s == 0) { mbar_wait(mbar0 + 0, ph0); ph0 ^= 1; }
        else        { mbar_wait(mbar0 + 8, ph1); ph1 ^= 1; }

        const int v = t * TILE_V + tid;
        if (v < NV) {
            const char* st = smem + s * STAGE_BYTES + tid * 16;
            float4 ke = *(const float4*)(st + 0 * ARR_BYTES);
            float4 al = *(const float4*)(st + 1 * ARR_BYTES);
            float4 cv = *(const float4*)(st + 2 * ARR_BYTES);
            float4 ey = *(const float4*)(st + 3 * ARR_BYTES);
            float4 ex = *(const float4*)(st + 4 * ARR_BYTES);
            int4  itg = *(const int4*)(st + 5 * ARR_BYTES);
            int4  ith = *(const int4*)(st + 6 * ARR_BYTES);
            int4  ieg = *(const int4*)(st + 7 * ARR_BYTES);
            int4  ih  = *(const int4*)(st + 8 * ARR_BYTES);

            const float* kef = &ke.x; const float* alf = &al.x;
            const float* cvf = &cv.x; const float* eyf = &ey.x;
            const float* exf = &ex.x;
            const int* itgf = &itg.x; const int* ithf = &ith.x;
            const int* iegf = &ieg.x; const int* ihf  = &ih.x;

            #pragma unroll
            for (int l = 0; l < 4; l++) {
                int tfi = ihf[l] ? (N_TG + ithf[l]) : itgf[l];
                float2 tf = __half22float2(s_tab[tfi]);      // (mu, sig^2)
                float2 tg = __half22float2(s_tab[iegf[l]]);  // (mu, sig^2)

                float iv  = fast_rcp(tf.y);
                float loc = fmaf(kef[l] * cvf[l], (eyf[l] - tf.x) * iv, tg.x);
                loc = fmaxf(loc, 0.0f) + 0.01f;
                float var = fmaf(-alf[l] * alf[l], iv, tg.y);
                var = fmaxf(var, 0.0f) + 0.01f;

                float dx = exf[l] - loc;
                acc += fmaf(0.5f, fmaf(dx * dx, fast_rcp(var), fast_logf(var)),
                            HALF_LOG2PI);
            }
        }
        __syncthreads();   // block done reading stage s

        const int tn = t + STAGES * GRID;
        if (tid == 0 && tn < NTILES) {
            fence_async_shared();
            uint32_t bytes = (uint32_t)min(TILE_V, NV - tn * TILE_V) * 16;
            size_t   off   = (size_t)tn * ARR_BYTES;
            uint32_t dst   = smem_base + s * STAGE_BYTES;
            mbar_expect_tx(mbar0 + s * 8, ARRS * bytes);
            #pragma unroll
            for (int a = 0; a < ARRS; a++)
                tma_1d(dst + a * ARR_BYTES, srcs[a] + off, bytes, mbar0 + s * 8);
        }
    }

    // ---- block reduction -> cross-block self-resetting accumulate ----
    acc = warp_reduce(acc);
    int lane = tid & 31, wid = tid >> 5;
    if (lane == 0) warp_sums[wid] = acc;
    __syncthreads();
    if (wid == 0) {
        float v = (lane < THREADS / 32) ? warp_sums[lane] : 0.0f;
        v = warp_reduce(v);
        if (lane == 0) {
            atomicAdd(&g_sum, v);
            __threadfence();
            unsigned t = atomicInc(&g_ticket, GRID - 1);   // wraps to 0
            if (t == GRID - 1)
                out[0] = atomicExch(&g_sum, 0.0f);         // publish + reset
        }
    }
}

extern "C" void kernel_launch(void* const* d_in, const int* in_sizes, int n_in,
                              void* d_out, int out_size) {
    cudaFuncSetAttribute(fused_loss_kernel,
                         cudaFuncAttributeMaxDynamicSharedMemorySize, SMEM_TOTAL);

    fused_loss_kernel<<<GRID, THREADS, SMEM_TOTAL>>>(
        (const float*)d_in[0], (const float*)d_in[1],
        (const float*)d_in[2], (const float*)d_in[3],
        (const float*)d_in[4], (const float*)d_in[5],
        (const char*)d_in[6],  (const char*)d_in[7],
        (const char*)d_in[8],  (const char*)d_in[9],
        (const char*)d_in[10], (const int*)d_in[11],
        (const char*)d_in[12], (const char*)d_in[13],
        (const char*)d_in[14], (const char*)d_in[15],
        (float*)d_out);
}